// round 12
// baseline (speedup 1.0000x reference)
#include <cuda_runtime.h>
#include <float.h>

// ---------------------------------------------------------------------------
// Fused single-kernel quantizer with DYNAMIC chunk scheduling.
//   phase 1: work-stolen min/max reduce over 16KB chunks (populate L2)
//   grid barrier (generation ticket, monotonic -> graph-replay safe)
//   phase 2: work-stolen quantize, chunks consumed in REVERSE index order
//            (L2-hot tail first), __ldcs reads / __stcs writes
// Rationale: R8 showed occ 48->72% with dur/DRAM%/issue% all flat ->
// bound is phase straggler time under static partitioning + grid barrier,
// not warp count. Work stealing levels both phases to ~1 chunk of skew.
// ---------------------------------------------------------------------------
#define CTAS_PER_SM 6
#define NBLOCKS (148 * CTAS_PER_SM)    // 888, co-resident by construction
#define CHUNK_F4 1024                  // 16KB: 4 float4 per thread per chunk

__device__ float g_pmn[NBLOCKS];
__device__ float g_pmx[NBLOCKS];
__device__ unsigned int g_arrive;      // barrier ticket (monotonic)
__device__ unsigned int g_done;        // end-of-kernel ticket (monotonic)
__device__ unsigned int g_ctr1;        // phase-1 chunk queue (reset each launch)
__device__ unsigned int g_ctr2;        // phase-2 chunk queue (reset each launch)

__device__ __forceinline__ float quant1(float x, float mn, float step, float inv) {
    float d = x - mn;                 // >= 0 exactly
    float q = d * inv;
    float t = floorf(q);
    float frac = q - t;
    if (frac < 2e-4f || frac > 0.9998f) {
        q = __fdiv_rn(d, step);       // exact IEEE divide, matches reference
        t = floorf(q);
    }
    t = fmaxf(t, 0.0f);
    t = fminf(t, 255.0f);
    return mn + (t + 0.5f) * step;
}

__device__ __forceinline__ float4 quant4(float4 v, float mn, float step, float inv) {
    float4 r;
    r.x = quant1(v.x, mn, step, inv);
    r.y = quant1(v.y, mn, step, inv);
    r.z = quant1(v.z, mn, step, inv);
    r.w = quant1(v.w, mn, step, inv);
    return r;
}

__global__ void __launch_bounds__(256, CTAS_PER_SM)
fused_quant_kernel(const float4* __restrict__ x4, float4* __restrict__ o4, int n4,
                   const float* __restrict__ x, float* __restrict__ o, int n) {
    const int tid = threadIdx.x;
    const int G = gridDim.x;
    const int gtid = blockIdx.x * blockDim.x + tid;
    const int nchunks = (n4 + CHUNK_F4 - 1) / CHUNK_F4;

    __shared__ int s_next;
    __shared__ float smn[8], smx[8];

    // ===================== Phase 1: min/max reduce (work-stolen) ============
    float mn =  FLT_MAX;
    float mx = -FLT_MAX;

    if (tid == 0) s_next = (int)atomicAdd(&g_ctr1, 1u);
    __syncthreads();
    int c = s_next;
    while (c < nchunks) {
        __syncthreads();                 // s_next consumed by all
        if (tid == 0) s_next = (int)atomicAdd(&g_ctr1, 1u);  // pipeline next grab

        int base4 = c * CHUNK_F4;
        int i0 = base4 + tid;
        if (base4 + CHUNK_F4 <= n4) {    // full chunk: no guards
            float4 a = x4[i0];
            float4 b = x4[i0 + 256];
            float4 cc = x4[i0 + 512];
            float4 d = x4[i0 + 768];
            mn = fminf(mn, fminf(fminf(a.x, a.y), fminf(a.z, a.w)));
            mx = fmaxf(mx, fmaxf(fmaxf(a.x, a.y), fmaxf(a.z, a.w)));
            mn = fminf(mn, fminf(fminf(b.x, b.y), fminf(b.z, b.w)));
            mx = fmaxf(mx, fmaxf(fmaxf(b.x, b.y), fmaxf(b.z, b.w)));
            mn = fminf(mn, fminf(fminf(cc.x, cc.y), fminf(cc.z, cc.w)));
            mx = fmaxf(mx, fmaxf(fmaxf(cc.x, cc.y), fmaxf(cc.z, cc.w)));
            mn = fminf(mn, fminf(fminf(d.x, d.y), fminf(d.z, d.w)));
            mx = fmaxf(mx, fmaxf(fmaxf(d.x, d.y), fmaxf(d.z, d.w)));
        } else {                         // last partial chunk
            #pragma unroll
            for (int k = 0; k < 4; k++) {
                int i = i0 + k * 256;
                if (i < n4) {
                    float4 v = x4[i];
                    mn = fminf(mn, fminf(fminf(v.x, v.y), fminf(v.z, v.w)));
                    mx = fmaxf(mx, fmaxf(fmaxf(v.x, v.y), fmaxf(v.z, v.w)));
                }
            }
        }
        __syncthreads();
        c = s_next;
    }
    int base = n4 << 2;
    if (gtid < (n - base)) {             // scalar tail (n % 4 != 0)
        float v = x[base + gtid];
        mn = fminf(mn, v);
        mx = fmaxf(mx, v);
    }

    // Block reduce -> per-block partial
    #pragma unroll
    for (int o_ = 16; o_ > 0; o_ >>= 1) {
        mn = fminf(mn, __shfl_xor_sync(0xFFFFFFFFu, mn, o_));
        mx = fmaxf(mx, __shfl_xor_sync(0xFFFFFFFFu, mx, o_));
    }
    int w = tid >> 5;
    int l = tid & 31;
    if (l == 0) { smn[w] = mn; smx[w] = mx; }
    __syncthreads();
    if (w == 0) {
        mn = (l < 8) ? smn[l] :  FLT_MAX;
        mx = (l < 8) ? smx[l] : -FLT_MAX;
        #pragma unroll
        for (int o_ = 4; o_ > 0; o_ >>= 1) {
            mn = fminf(mn, __shfl_xor_sync(0xFFFFFFFFu, mn, o_));
            mx = fmaxf(mx, __shfl_xor_sync(0xFFFFFFFFu, mx, o_));
        }
        if (l == 0) {
            g_pmn[blockIdx.x] = mn;
            g_pmx[blockIdx.x] = mx;
        }
    }

    // ===================== Grid barrier (generation ticket) =================
    // All NBLOCKS CTAs co-resident -> spin cannot deadlock. Monotonic
    // counter: replay k waits for k*G arrivals -> no reset, replay-safe.
    if (tid == 0) {
        __threadfence();                               // publish partials
        unsigned int ticket = atomicAdd(&g_arrive, 1u);
        unsigned int target = (ticket / G + 1u) * G;
        while (*(volatile unsigned int*)&g_arrive < target) {
            __nanosleep(32);
        }
        __threadfence();                               // acquire partials
    }
    __syncthreads();

    // ===================== Fold partials (every block) ======================
    mn =  FLT_MAX;
    mx = -FLT_MAX;
    #pragma unroll 1
    for (int j = tid; j < G; j += 256) {
        mn = fminf(mn, g_pmn[j]);
        mx = fmaxf(mx, g_pmx[j]);
    }
    #pragma unroll
    for (int o_ = 16; o_ > 0; o_ >>= 1) {
        mn = fminf(mn, __shfl_xor_sync(0xFFFFFFFFu, mn, o_));
        mx = fmaxf(mx, __shfl_xor_sync(0xFFFFFFFFu, mx, o_));
    }
    __syncthreads();                    // smn/smx reuse
    if (l == 0) { smn[w] = mn; smx[w] = mx; }
    __syncthreads();
    mn = smn[0]; mx = smx[0];
    #pragma unroll
    for (int j = 1; j < 8; j++) {
        mn = fminf(mn, smn[j]);
        mx = fmaxf(mx, smx[j]);
    }

    // step = (max - min)/256 exactly (power-of-2 scale)
    float step = (mx - mn) * (1.0f / 256.0f);
    float inv  = __fdiv_rn(1.0f, step);

    // ===================== Phase 2: quantize (work-stolen, reverse) =========
    if (gtid < (n - base)) {
        o[base + gtid] = quant1(x[base + gtid], mn, step, inv);
    }
    if (tid == 0) s_next = (int)atomicAdd(&g_ctr2, 1u);
    __syncthreads();
    c = s_next;
    while (c < nchunks) {
        __syncthreads();
        if (tid == 0) s_next = (int)atomicAdd(&g_ctr2, 1u);

        int rc = nchunks - 1 - c;        // consume hot (last-read) chunks first
        int base4 = rc * CHUNK_F4;
        int i0 = base4 + tid;
        if (base4 + CHUNK_F4 <= n4) {
            float4 a = __ldcs(&x4[i0]);
            float4 b = __ldcs(&x4[i0 + 256]);
            float4 cc = __ldcs(&x4[i0 + 512]);
            float4 d = __ldcs(&x4[i0 + 768]);
            __stcs(&o4[i0],       quant4(a, mn, step, inv));
            __stcs(&o4[i0 + 256], quant4(b, mn, step, inv));
            __stcs(&o4[i0 + 512], quant4(cc, mn, step, inv));
            __stcs(&o4[i0 + 768], quant4(d, mn, step, inv));
        } else {
            #pragma unroll
            for (int k = 0; k < 4; k++) {
                int i = i0 + k * 256;
                if (i < n4) {
                    __stcs(&o4[i], quant4(__ldcs(&x4[i]), mn, step, inv));
                }
            }
        }
        __syncthreads();
        c = s_next;
    }

    // ===================== Reset queues (last-done CTA) =====================
    // Each CTA's last g_ctr2 use happens-before its done ticket (threadfence).
    // The CTA taking the final ticket of this launch resets both queues; the
    // kernel boundary orders the reset before the next replay's reads.
    __syncthreads();
    if (tid == 0) {
        __threadfence();
        unsigned int d = atomicAdd(&g_done, 1u);
        if ((d + 1u) % (unsigned int)G == 0u) {
            atomicExch(&g_ctr1, 0u);
            atomicExch(&g_ctr2, 0u);
        }
    }
}

// ---------------------------------------------------------------------------
// Launch
// ---------------------------------------------------------------------------
extern "C" void kernel_launch(void* const* d_in, const int* in_sizes, int n_in,
                              void* d_out, int out_size) {
    const float* x = (const float*)d_in[0];
    float* out = (float*)d_out;
    const int n  = in_sizes[0];
    const int n4 = n >> 2;

    fused_quant_kernel<<<NBLOCKS, 256>>>((const float4*)x, (float4*)out, n4,
                                         x, out, n);
}